// round 17
// baseline (speedup 1.0000x reference)
#include <cuda_runtime.h>

#define T_LEN 1024
#define B_SZ  32
#define H_SZ  8
#define D_SZ  32
#define YD_SZ 97
#define IN_SZ 256
#define NTHREADS 256  // 8 warps, 2 chains per CTA

typedef unsigned long long u64;

// FWM per-step outputs (T,B,H*D) = (T*B, 256) row-major
__device__ float g_scratch[T_LEN * B_SZ * IN_SZ];

// ---- packed f32x2 primitives (Blackwell FFMA2; PTX-only path) ----
__device__ __forceinline__ void ffma2(u64 &d, u64 a, u64 b) {
    asm("fma.rn.f32x2 %0, %1, %2, %0;" : "+l"(d) : "l"(a), "l"(b));
}
__device__ __forceinline__ u64 add2(u64 a, u64 b) {
    u64 r; asm("add.rn.f32x2 %0, %1, %2;" : "=l"(r) : "l"(a), "l"(b));
    return r;
}
__device__ __forceinline__ float2 u2f2(u64 v) {
    float2 r; asm("mov.b64 {%0, %1}, %2;" : "=f"(r.x), "=f"(r.y) : "l"(v));
    return r;
}
__device__ __forceinline__ u64 f2u2(float lo, float hi) {
    u64 r; asm("mov.b64 %0, {%1, %2};" : "=l"(r) : "f"(lo), "f"(hi));
    return r;
}
__device__ __forceinline__ float hsum2(u64 a, u64 b) {
    float2 s = u2f2(add2(a, b));
    return s.x + s.y;
}

// Dual no-max softmax: the two SHFL reduction chains (independent) are
// interleaved so both finish in ~one chain's latency.
__device__ __forceinline__ float2 dual_softmax32(float vA, float vB) {
    float eA = __expf(fminf(vA, 80.0f));
    float eB = __expf(fminf(vB, 80.0f));
    float sA = eA, sB = eB;
#pragma unroll
    for (int o = 16; o > 0; o >>= 1) {
        sA += __shfl_xor_sync(0xffffffffu, sA, o);
        sB += __shfl_xor_sync(0xffffffffu, sB, o);
    }
    return make_float2(__fdividef(eA, sA), __fdividef(eB, sB));
}

// ---- column-state initializers ----
__device__ __forceinline__ void init_qk(u64* col, const float* g, const float* s, int j) {
#pragma unroll
    for (int i = 0; i < 16; i++)
        col[i] = f2u2(g[(2*i)*D_SZ + j]   + s[(2*i)*D_SZ + j],
                      g[(2*i+1)*D_SZ + j] + s[(2*i+1)*D_SZ + j]);
}
__device__ __forceinline__ void init_wy(u64* col, const float* g, const float* s, int j) {
#pragma unroll
    for (int i = 0; i < 16; i++)
        col[i] = f2u2(g[(2*i)*YD_SZ + j]   + s[(2*i)*YD_SZ + j],
                      g[(2*i+1)*YD_SZ + j] + s[(2*i+1)*YD_SZ + j]);
}
__device__ __forceinline__ void init_wb(u64* col, const float* g, const float* s, int j) {
#pragma unroll
    for (int i = 0; i < 16; i++)
        col[i] = f2u2(g[(2*i)*4 + j]   + s[(2*i)*4 + j],
                      g[(2*i+1)*4 + j] + s[(2*i+1)*4 + j]);
}
__device__ __forceinline__ void init_f(u64* col, const float* f, int j) {
#pragma unroll
    for (int i = 0; i < 16; i++)
        col[i] = f2u2(f[(2*i)*D_SZ + j], f[(2*i+1)*D_SZ + j]);
}

// One fast-weight-memory step for one chain (reads softmaxed fq/fk + raw fv + fb).
__device__ __forceinline__ void fwm_step(u64* col, const float* fksrc, const float* fqsrc,
                                         float fbv, float fvv, float* dst) {
    const ulonglong2* fk2 = reinterpret_cast<const ulonglong2*>(fksrc);
    const ulonglong2* fq2 = reinterpret_cast<const ulonglong2*>(fqsrc);
    ulonglong2 kr[8];
    u64 vA = 0ull, vB = 0ull;
#pragma unroll
    for (int i = 0; i < 8; i++) {
        kr[i] = fk2[i];
        ffma2(vA, kr[i].x, col[2*i + 0]);
        ffma2(vB, kr[i].y, col[2*i + 1]);
    }
    const float coeff = fbv * (fvv - hsum2(vA, vB));
    const u64 c2 = f2u2(coeff, coeff);
    u64 oA = 0ull, oB = 0ull;
#pragma unroll
    for (int i = 0; i < 8; i++) {
        ffma2(col[2*i + 0], kr[i].x, c2);
        ffma2(col[2*i + 1], kr[i].y, c2);
        ulonglong2 qv = fq2[i];
        ffma2(oA, qv.x, col[2*i + 0]);
        ffma2(oB, qv.y, col[2*i + 1]);
    }
    *dst = hsum2(oA, oB);
}

// Roles by wid: 0=q 1=k 2=fq 3=fk 4=fv 5=beta/fb 6=FWM 7=x-pipe.
// Each warp executes its role for BOTH chains (A = 2*bid, B = 2*bid+1) with
// manually interleaved instructions: in-order issue always has the other
// chain's independent ops to fill latency slots.
__global__ __launch_bounds__(NTHREADS, 1)
void srwm_scan_kernel(const float* __restrict__ h_in,
                      const float* __restrict__ W_y,
                      const float* __restrict__ W_q,
                      const float* __restrict__ W_k,
                      const float* __restrict__ w_b,
                      const float* __restrict__ sWy,
                      const float* __restrict__ sWq,
                      const float* __restrict__ sWk,
                      const float* __restrict__ swb,
                      const float* __restrict__ Fw)
{
    const int tid  = threadIdx.x;
    const int wid  = tid >> 5;
    const int lane = tid & 31;
    const int bhA  = blockIdx.x * 2;       // chain A
    const int bhB  = bhA + 1;              // chain B
    const int bA = bhA >> 3, hA = bhA & 7;
    const int bB = bhB >> 3, hB = bhB & 7;

    // [chain][parity][lane]
    __shared__ __align__(16) float xbuf[2][2][D_SZ];
    __shared__ __align__(16) float qsh[2][2][D_SZ], ksh[2][2][D_SZ];
    __shared__ __align__(16) float fqsh[2][2][D_SZ], fksh[2][2][D_SZ], fvsh[2][2][D_SZ];
    __shared__ float betash[2][2][4];
    __shared__ float fbsh[2][2];

    u64 colA[16], colB[16];
#pragma unroll
    for (int i = 0; i < 16; i++) { colA[i] = 0ull; colB[i] = 0ull; }

    // ---- init state columns (per role, both chains) ----
    if (wid == 0) {
        init_qk(colA, W_q + hA * D_SZ * D_SZ, sWq + (size_t)(bA * H_SZ + hA) * D_SZ * D_SZ, lane);
        init_qk(colB, W_q + hB * D_SZ * D_SZ, sWq + (size_t)(bB * H_SZ + hB) * D_SZ * D_SZ, lane);
    } else if (wid == 1) {
        init_qk(colA, W_k + hA * D_SZ * D_SZ, sWk + (size_t)(bA * H_SZ + hA) * D_SZ * D_SZ, lane);
        init_qk(colB, W_k + hB * D_SZ * D_SZ, sWk + (size_t)(bB * H_SZ + hB) * D_SZ * D_SZ, lane);
    } else if (wid >= 2 && wid <= 4) {     // fq / fk / fv: Wy cols
        const int j = (wid - 2) * 32 + lane;
        init_wy(colA, W_y + hA * D_SZ * YD_SZ, sWy + (size_t)(bA * H_SZ + hA) * D_SZ * YD_SZ, j);
        init_wy(colB, W_y + hB * D_SZ * YD_SZ, sWy + (size_t)(bB * H_SZ + hB) * D_SZ * YD_SZ, j);
    } else if (wid == 5 && lane < 5) {
        if (lane == 0) {                   // fb: Wy col 96
            init_wy(colA, W_y + hA * D_SZ * YD_SZ, sWy + (size_t)(bA * H_SZ + hA) * D_SZ * YD_SZ, 96);
            init_wy(colB, W_y + hB * D_SZ * YD_SZ, sWy + (size_t)(bB * H_SZ + hB) * D_SZ * YD_SZ, 96);
        } else {                           // wb col lane-1
            init_wb(colA, w_b + hA * D_SZ * 4, swb + (size_t)(bA * H_SZ + hA) * D_SZ * 4, lane - 1);
            init_wb(colB, w_b + hB * D_SZ * 4, swb + (size_t)(bB * H_SZ + hB) * D_SZ * 4, lane - 1);
        }
    } else if (wid == 6) {                 // FWM
        init_f(colA, Fw + (size_t)(bA * H_SZ + hA) * D_SZ * D_SZ, lane);
        init_f(colB, Fw + (size_t)(bB * H_SZ + hB) * D_SZ * D_SZ, lane);
    }

    // x-pipe: x[0] softmax for both chains + h[1] prefetch.
    float xregA = 0.f, xregB = 0.f;
    const float* hbA = h_in + (size_t)bA * IN_SZ + hA * D_SZ + lane;
    const float* hbB = h_in + (size_t)bB * IN_SZ + hB * D_SZ + lane;
    if (wid == 7) {
        float2 sm = dual_softmax32(hbA[0], hbB[0]);
        xbuf[0][0][lane] = sm.x;
        xbuf[1][0][lane] = sm.y;
        xregA = hbA[(size_t)B_SZ * IN_SZ];
        xregB = hbB[(size_t)B_SZ * IN_SZ];
    }
    float* scrA = g_scratch + (size_t)bA * IN_SZ + hA * D_SZ + lane;
    float* scrB = g_scratch + (size_t)bB * IN_SZ + hB * D_SZ + lane;
    const u64 NEG1 = f2u2(-1.0f, -1.0f);
    __syncthreads();

    for (int t = 0; t < T_LEN; ++t) {
        const int p = t & 1;

        // ---- phase 1 ----
        if (wid <= 4) {
            const ulonglong2* xA = reinterpret_cast<const ulonglong2*>(xbuf[0][p]);
            const ulonglong2* xB = reinterpret_cast<const ulonglong2*>(xbuf[1][p]);
            u64 aA0 = 0ull, aA1 = 0ull, aB0 = 0ull, aB1 = 0ull;
#pragma unroll
            for (int i = 0; i < 8; i++) {
                ulonglong2 xa = xA[i], xb = xB[i];
                ffma2(aA0, xa.x, colA[2*i + 0]);
                ffma2(aB0, xb.x, colB[2*i + 0]);
                ffma2(aA1, xa.y, colA[2*i + 1]);
                ffma2(aB1, xb.y, colB[2*i + 1]);
            }
            float rawA = hsum2(aA0, aA1);
            float rawB = hsum2(aB0, aB1);
            if (wid == 4) {
                fvsh[0][p][lane] = rawA;
                fvsh[1][p][lane] = rawB;
            } else {
                float2 sm = dual_softmax32(rawA, rawB);
                if      (wid == 0) { qsh[0][p][lane]  = sm.x; qsh[1][p][lane]  = sm.y; }
                else if (wid == 1) { ksh[0][p][lane]  = sm.x; ksh[1][p][lane]  = sm.y; }
                else if (wid == 2) { fqsh[0][p][lane] = sm.x; fqsh[1][p][lane] = sm.y; }
                else               { fksh[0][p][lane] = sm.x; fksh[1][p][lane] = sm.y; }
            }
        } else if (wid == 5) {
            if (lane < 5) {
                const ulonglong2* xA = reinterpret_cast<const ulonglong2*>(xbuf[0][p]);
                const ulonglong2* xB = reinterpret_cast<const ulonglong2*>(xbuf[1][p]);
                u64 aA0 = 0ull, aA1 = 0ull, aB0 = 0ull, aB1 = 0ull;
#pragma unroll
                for (int i = 0; i < 8; i++) {
                    ulonglong2 xa = xA[i], xb = xB[i];
                    ffma2(aA0, xa.x, colA[2*i + 0]);
                    ffma2(aB0, xb.x, colB[2*i + 0]);
                    ffma2(aA1, xa.y, colA[2*i + 1]);
                    ffma2(aB1, xb.y, colB[2*i + 1]);
                }
                float rawA = hsum2(aA0, aA1);
                float rawB = hsum2(aB0, aB1);
                float sgA = 1.0f / (1.0f + __expf(-rawA));
                float sgB = 1.0f / (1.0f + __expf(-rawB));
                if (lane == 0) { fbsh[0][p] = sgA; fbsh[1][p] = sgB; }
                else { betash[0][p][lane - 1] = sgA; betash[1][p][lane - 1] = sgB; }
            }
        } else if (wid == 7) {
            // x_{t+1} softmax (both chains) + prefetch h[t+2]
            float2 sm = dual_softmax32(xregA, xregB);
            xbuf[0][p ^ 1][lane] = sm.x;
            xbuf[1][p ^ 1][lane] = sm.y;
            if (t + 2 < T_LEN) {
                xregA = hbA[(size_t)(t + 2) * B_SZ * IN_SZ];
                xregB = hbB[(size_t)(t + 2) * B_SZ * IN_SZ];
            }
        } else if (t > 0) {   // wid == 6 : lagged FWM for step t-1, both chains
            const int pp = p ^ 1;
            fwm_step(colA, fksh[0][pp], fqsh[0][pp], fbsh[0][pp], fvsh[0][pp][lane],
                     scrA + (size_t)(t - 1) * B_SZ * IN_SZ);
            fwm_step(colB, fksh[1][pp], fqsh[1][pp], fbsh[1][pp], fvsh[1][pp][lane],
                     scrB + (size_t)(t - 1) * B_SZ * IN_SZ);
        }
        __syncthreads();   // the ONLY barrier per step (covers both chains)

        // ---- phase 2: rank-1 SRWM updates, fused (q-k) matvec, both chains ----
        if (wid <= 4 || (wid == 5 && lane < 5)) {
            const int bidx = (wid == 0) ? 1
                           : (wid == 1) ? 2
                           : (wid == 5) ? ((lane == 0) ? 0 : 3)
                                        : 0;   // wid 2,3,4 (Wy)
            const float bselA = betash[0][p][bidx];
            const float bselB = betash[1][p][bidx];
            const ulonglong2* q2A = reinterpret_cast<const ulonglong2*>(qsh[0][p]);
            const ulonglong2* k2A = reinterpret_cast<const ulonglong2*>(ksh[0][p]);
            const ulonglong2* q2B = reinterpret_cast<const ulonglong2*>(qsh[1][p]);
            const ulonglong2* k2B = reinterpret_cast<const ulonglong2*>(ksh[1][p]);
            ulonglong2 krA[8], krB[8];
            u64 dA0 = 0ull, dA1 = 0ull, dB0 = 0ull, dB1 = 0ull;
#pragma unroll
            for (int i = 0; i < 8; i++) {
                ulonglong2 qa = q2A[i], ka = k2A[i];
                ulonglong2 qb = q2B[i], kb = k2B[i];
                krA[i] = ka; krB[i] = kb;
                u64 t0 = qa.x; ffma2(t0, ka.x, NEG1); ffma2(dA0, t0, colA[2*i + 0]);
                u64 t1 = qb.x; ffma2(t1, kb.x, NEG1); ffma2(dB0, t1, colB[2*i + 0]);
                u64 t2 = qa.y; ffma2(t2, ka.y, NEG1); ffma2(dA1, t2, colA[2*i + 1]);
                u64 t3 = qb.y; ffma2(t3, kb.y, NEG1); ffma2(dB1, t3, colB[2*i + 1]);
            }
            const float diffA = bselA * hsum2(dA0, dA1);
            const float diffB = bselB * hsum2(dB0, dB1);
            const u64 d2A = f2u2(diffA, diffA);
            const u64 d2B = f2u2(diffB, diffB);
#pragma unroll
            for (int i = 0; i < 8; i++) {
                ffma2(colA[2*i + 0], krA[i].x, d2A);
                ffma2(colB[2*i + 0], krB[i].x, d2B);
                ffma2(colA[2*i + 1], krA[i].y, d2A);
                ffma2(colB[2*i + 1], krB[i].y, d2B);
            }
        }
        // phase1(t+1) writes parity p^1; phase2(t) reads parity p.
        // All cross-parity hazards are separated by the barrier above.
    }

    // Epilogue: FWM for the final step t = T-1, both chains.
    if (wid == 6) {
        const int pp = (T_LEN - 1) & 1;
        fwm_step(colA, fksh[0][pp], fqsh[0][pp], fbsh[0][pp], fvsh[0][pp][lane],
                 scrA + (size_t)(T_LEN - 1) * B_SZ * IN_SZ);
        fwm_step(colB, fksh[1][pp], fqsh[1][pp], fbsh[1][pp], fvsh[1][pp][lane],
                 scrB + (size_t)(T_LEN - 1) * B_SZ * IN_SZ);
    }
}

// ======================= output projection ==========================
// out[r, i] = h[r, i] + sum_j scratch[r, j] * W_out[i, j]
// (T*B=32768) x 256 x 256 sgemm, 128x128 tiles, 8x8 micro-tiles.
// A-fragments read as packed row-pairs (LDS.128 -> native FFMA2 operands);
// accumulators packed across rows; B splatted. GBK=16 halves barrier count.
#define GBM 128
#define GBN 128
#define GBK 16

__global__ __launch_bounds__(256)
void proj_kernel(const float* __restrict__ W,
                 const float* __restrict__ Hin,
                 float* __restrict__ out)
{
    __shared__ __align__(16) float As[GBK][GBM];
    __shared__ __align__(16) float Bs[GBK][GBN];
    const int row0 = blockIdx.x * GBM;
    const int col0 = blockIdx.y * GBN;
    const int tid  = threadIdx.x;
    const int tr   = (tid / 16) * 8;
    const int tc   = (tid % 16) * 8;

    // acc2[u2][v] = packed (row tr+2*u2, row tr+2*u2+1) for column tc+v
    u64 acc2[4][8];
#pragma unroll
    for (int u = 0; u < 4; u++)
#pragma unroll
        for (int v = 0; v < 8; v++) acc2[u][v] = 0ull;

    const int ar = tid >> 1;          // row / column within tile (0..127)
    const int ak = (tid & 1) * 8;     // k half (0 or 8)

    for (int k0 = 0; k0 < IN_SZ; k0 += GBK) {
        const float* as = &g_scratch[(row0 + ar) * IN_SZ + k0 + ak];
        const float* ws = &W[(col0 + ar) * IN_SZ + k0 + ak];
        float4 av0 = *reinterpret_cast<const float4*>(as);
        float4 av1 = *reinterpret_cast<const float4*>(as + 4);
        float4 bv0 = *reinterpret_cast<const float4*>(ws);
        float4 bv1 = *reinterpret_cast<const float4*>(ws + 4);
        As[ak + 0][ar] = av0.x; As[ak + 1][ar] = av0.y;
        As[ak + 2][ar] = av0.z; As[ak + 3][ar] = av0.w;
        As[ak + 4][ar] = av1.x; As[ak + 5][ar] = av1.y;
        As[ak + 6][ar] = av1.z; As[ak + 7][ar] = av1.w;
        Bs[ak + 0][ar] = bv0.x; Bs[ak + 1][ar] = bv0.y;
        Bs[ak + 2][ar] = bv0.z; Bs[ak + 3][ar] = bv0.w;
        Bs[ak + 4][ar] = bv1.x; Bs[ak + 5][ar] = bv1.y;
        Bs[ak + 6][ar] = bv1.z; Bs[ak + 7][ar] = bv1.w;
        __syncthreads();
#pragma unroll
        for (int k = 0; k < GBK; k++) {
            ulonglong2 a01 = *reinterpret_cast<const ulonglong2*>(&As[k][tr]);
            ulonglong2 a23 = *reinterpret_cast<const ulonglong2*>(&As[k][tr + 4]);
            u64 ap[4] = {a01.x, a01.y, a23.x, a23.y};
            float4 b0 = *reinterpret_cast<const float4*>(&Bs[k][tc]);
            float4 b1 = *reinterpret_cast<const float4*>(&Bs[k][tc + 4]);
            u64 bs[8];
            bs[0] = f2u2(b0.x, b0.x); bs[1] = f2u2(b0.y, b0.y);
            bs[2] = f2u2(b0.z, b0.z); bs[3] = f2u2(b0.w, b0.w);
            bs[4] = f2u2(b1.x, b1.x); bs[5] = f2u2(b1.y, b1.y);
            bs[6] = f2u2(b1.z, b1.z); bs[7] = f2u2(b1.w, b1.w);
#pragma unroll
            for (int u = 0; u < 4; u++)
#pragma unroll
                for (int v = 0; v < 8; v++)
                    ffma2(acc2[u][v], ap[u], bs[v]);
        }
        __syncthreads();
    }

#pragma unroll
    for (int u = 0; u < 4; u++) {
        const int r0 = row0 + tr + 2 * u;
        float lo[8], hi[8];
#pragma unroll
        for (int v = 0; v < 8; v++) {
            float2 t = u2f2(acc2[u][v]);
            lo[v] = t.x; hi[v] = t.y;
        }
#pragma unroll
        for (int half = 0; half < 2; half++) {
            const int c = col0 + tc + half * 4;
            float4 h0 = *reinterpret_cast<const float4*>(&Hin[r0 * IN_SZ + c]);
            float4 h1 = *reinterpret_cast<const float4*>(&Hin[(r0 + 1) * IN_SZ + c]);
            float4 o0, o1;
            o0.x = h0.x + lo[half*4+0]; o0.y = h0.y + lo[half*4+1];
            o0.z = h0.z + lo[half*4+2]; o0.w = h0.w + lo[half*4+3];
            o1.x = h1.x + hi[half*4+0]; o1.y = h1.y + hi[half*4+1];
            o1.z = h1.z + hi[half*4+2]; o1.w = h1.w + hi[half*4+3];
            *reinterpret_cast<float4*>(&out[r0 * IN_SZ + c]) = o0;
            *reinterpret_cast<float4*>(&out[(r0 + 1) * IN_SZ + c]) = o1;
        }
    }
}

extern "C" void kernel_launch(void* const* d_in, const int* in_sizes, int n_in,
                              void* d_out, int out_size) {
    const float* h_in  = (const float*)d_in[0];
    const float* W_y   = (const float*)d_in[1];
    const float* W_q   = (const float*)d_in[2];
    const float* W_k   = (const float*)d_in[3];
    const float* w_b   = (const float*)d_in[4];
    const float* W_out = (const float*)d_in[5];
    const float* sWy   = (const float*)d_in[6];
    const float* sWq   = (const float*)d_in[7];
    const float* sWk   = (const float*)d_in[8];
    const float* swb   = (const float*)d_in[9];
    const float* Fw    = (const float*)d_in[10];

    srwm_scan_kernel<<<(B_SZ * H_SZ) / 2, NTHREADS>>>(
        h_in, W_y, W_q, W_k, w_b, sWy, sWq, sWk, swb, Fw);

    dim3 grid((T_LEN * B_SZ) / GBM, IN_SZ / GBN);
    proj_kernel<<<grid, 256>>>(W_out, h_in, (float*)d_out);
}